// round 2
// baseline (speedup 1.0000x reference)
#include <cuda_runtime.h>
#include <cstdint>

// Problem constants (fixed by reference setup_inputs)
#define B_SZ   16
#define T_IN   512
#define D_DIM  768
#define D4     (D_DIM / 4)     // 192 float4 per row
#define T_MAX  4096            // T_IN * MAX_DUR upper bound

// Scratch: frame -> phoneme index map, -1 = padding frame
__device__ int g_idx[B_SZ * T_MAX];

// Kernel 1: per-batch inclusive scan of durations + scatter frame->phoneme map.
// One block per batch, 512 threads (one per input phoneme).
// NOTE: durations are int32 on device (JAX default config downgrades int64).
__global__ void build_idx_kernel(const int* __restrict__ durations, int t_out) {
    __shared__ int cum[T_IN];
    const int b   = blockIdx.x;
    const int tid = threadIdx.x;

    const int dur = durations[b * T_IN + tid];
    cum[tid] = dur;
    __syncthreads();

    // Hillis-Steele inclusive scan over 512 elements
    #pragma unroll
    for (int off = 1; off < T_IN; off <<= 1) {
        int add = (tid >= off) ? cum[tid - off] : 0;
        __syncthreads();
        cum[tid] += add;
        __syncthreads();
    }

    // Fill this batch's map with -1 (padding)
    int* my_idx = g_idx + b * T_MAX;
    for (int t = tid; t < t_out; t += T_IN)
        my_idx[t] = -1;
    __syncthreads();

    // Scatter: phoneme tid covers frames [cum-dur, cum)
    const int end   = cum[tid];
    const int start = end - dur;
    for (int t = start; t < end; ++t)
        my_idx[t] = tid;
}

// Kernel 2: row gather. grid = (T_out, B), block = 192 threads,
// one float4 per thread => 768B coalesced read + write per block.
__global__ void __launch_bounds__(D4) gather_kernel(
    const float4* __restrict__ hidden, float4* __restrict__ out, int t_out) {
    const int t = blockIdx.x;
    const int b = blockIdx.y;
    const int d = threadIdx.x;

    const int idx = g_idx[b * T_MAX + t];
    float4 v = make_float4(0.f, 0.f, 0.f, 0.f);
    if (idx >= 0)
        v = hidden[((size_t)b * T_IN + idx) * D4 + d];
    out[((size_t)b * t_out + t) * D4 + d] = v;
}

extern "C" void kernel_launch(void* const* d_in, const int* in_sizes, int n_in,
                              void* d_out, int out_size) {
    const float* hidden    = (const float*)d_in[0];  // (B, T_IN, D) f32
    const int*   durations = (const int*)d_in[1];    // (B, T_IN) int32 (JAX x64 disabled)

    const int t_out = out_size / (B_SZ * D_DIM);

    build_idx_kernel<<<B_SZ, T_IN>>>(durations, t_out);

    dim3 grid(t_out, B_SZ);
    gather_kernel<<<grid, D4>>>((const float4*)hidden, (float4*)d_out, t_out);
}

// round 3
// speedup vs baseline: 1.5504x; 1.5504x over previous
#include <cuda_runtime.h>
#include <cstdint>

// Problem constants (fixed by reference setup_inputs)
#define B_SZ   16
#define T_IN   512
#define D_DIM  768
#define D4     (D_DIM / 4)     // 192 float4 per row
#define T_MAX  4096            // T_IN * MAX_DUR upper bound
#define FRAMES 8               // frames per gather block (MLP per thread)

// Scratch: frame -> phoneme index map, -1 = padding frame
__device__ int g_idx[B_SZ * T_MAX];

// Kernel 1: per-batch inclusive scan of durations + scatter frame->phoneme map.
// One block per batch, 512 threads (one per input phoneme).
// durations are int32 on device (JAX default config downgrades int64).
__global__ void build_idx_kernel(const int* __restrict__ durations, int t_out) {
    __shared__ int cum[T_IN];
    const int b   = blockIdx.x;
    const int tid = threadIdx.x;

    const int dur = durations[b * T_IN + tid];
    cum[tid] = dur;
    __syncthreads();

    // Hillis-Steele inclusive scan over 512 elements
    #pragma unroll
    for (int off = 1; off < T_IN; off <<= 1) {
        int add = (tid >= off) ? cum[tid - off] : 0;
        __syncthreads();
        cum[tid] += add;
        __syncthreads();
    }

    // Fill this batch's map with -1 (padding)
    int* my_idx = g_idx + b * T_MAX;
    for (int t = tid; t < t_out; t += T_IN)
        my_idx[t] = -1;
    __syncthreads();

    // Scatter: phoneme tid covers frames [cum-dur, cum)
    const int end   = cum[tid];
    const int start = end - dur;
    for (int t = start; t < end; ++t)
        my_idx[t] = tid;
}

// Kernel 2: coarsened row gather. grid = (ceil(t_out/FRAMES), B), block = 192.
// Each thread handles FRAMES independent (t, d) float4s: all idx loads first,
// then all hidden loads (MLP=FRAMES), then streaming stores.
__global__ void __launch_bounds__(D4) gather_kernel(
    const float4* __restrict__ hidden, float4* __restrict__ out, int t_out) {
    const int t0 = blockIdx.x * FRAMES;
    const int b  = blockIdx.y;
    const int d  = threadIdx.x;

    const int*    my_idx  = g_idx + b * T_MAX;
    const float4* my_hid  = hidden + (size_t)b * T_IN * D4 + d;
    float4*       my_out  = out + ((size_t)b * t_out + t0) * D4 + d;

    // Phase 1: fetch all frame->phoneme indices (independent loads)
    int idx[FRAMES];
    #pragma unroll
    for (int f = 0; f < FRAMES; ++f) {
        int t = t0 + f;
        idx[f] = (t < t_out) ? my_idx[t] : -2;   // -2 = out of range, skip store
    }

    // Phase 2: issue all hidden loads (independent -> MLP = FRAMES)
    float4 v[FRAMES];
    #pragma unroll
    for (int f = 0; f < FRAMES; ++f) {
        v[f] = make_float4(0.f, 0.f, 0.f, 0.f);
        if (idx[f] >= 0)
            v[f] = __ldg(my_hid + (size_t)idx[f] * D4);
    }

    // Phase 3: streaming stores (output is write-once; keep hidden in L2)
    #pragma unroll
    for (int f = 0; f < FRAMES; ++f) {
        if (idx[f] != -2)
            __stcs(my_out + (size_t)f * D4, v[f]);
    }
}

extern "C" void kernel_launch(void* const* d_in, const int* in_sizes, int n_in,
                              void* d_out, int out_size) {
    const float* hidden    = (const float*)d_in[0];  // (B, T_IN, D) f32
    const int*   durations = (const int*)d_in[1];    // (B, T_IN) int32

    const int t_out = out_size / (B_SZ * D_DIM);

    build_idx_kernel<<<B_SZ, T_IN>>>(durations, t_out);

    dim3 grid((t_out + FRAMES - 1) / FRAMES, B_SZ);
    gather_kernel<<<grid, D4>>>((const float4*)hidden, (float4*)d_out, t_out);
}